// round 9
// baseline (speedup 1.0000x reference)
#include <cuda_runtime.h>
#include <cuda_fp16.h>

#define N 8192
#define C 10
#define Dd 6
#define JC 256    // j-chunk per gemv block
#define IT 512    // i-tile per gemv block (4 warps x 128)
#define BI 64

__device__ __half g_Ksp[(size_t)N * N];   // 134 MB
__device__ __half g_Kbl[(size_t)N * N];   // 134 MB
__device__ float g_P[C * N];
__device__ float g_OSP[C * N];
__device__ float g_OBL[C * N];
__device__ float g_A[C * C];
__device__ float g_B[C * C];

// ---- f32x2 packed helpers ----
__device__ __forceinline__ unsigned long long pk2(float lo, float hi) {
    unsigned long long r;
    asm("mov.b64 %0, {%1, %2};" : "=l"(r) : "f"(lo), "f"(hi));
    return r;
}
__device__ __forceinline__ float2 upk2(unsigned long long v) {
    float2 r;
    asm("mov.b64 {%0, %1}, %2;" : "=f"(r.x), "=f"(r.y) : "l"(v));
    return r;
}
__device__ __forceinline__ unsigned long long ffma2(unsigned long long a,
                                                    unsigned long long b,
                                                    unsigned long long c) {
    unsigned long long d;
    asm("fma.rn.f32x2 %0, %1, %2, %3;" : "=l"(d) : "l"(a), "l"(b), "l"(c));
    return d;
}

// ---------------------------------------------------------------------------
// Build both kernel matrices (fp16) once. Dot-product distance form.
// ---------------------------------------------------------------------------
__global__ __launch_bounds__(256) void build_K(const float* __restrict__ feat) {
    __shared__ float fis[Dd][BI];
    __shared__ float a3s[BI], a6s[BI];

    const int ib = blockIdx.y * BI;
    const int jp = blockIdx.x * 256 + threadIdx.x;
    const int j0 = jp * 2;

    if (threadIdx.x < BI) {
        float s3 = 0.f, s6 = 0.f;
#pragma unroll
        for (int d = 0; d < Dd; d++) {
            float v = feat[d * N + ib + threadIdx.x];
            fis[d][threadIdx.x] = v;
            if (d < 3) s3 += v * v; else s6 += v * v;
        }
        a3s[threadIdx.x] = s3;
        a6s[threadIdx.x] = s3 + s6;
    }
    __syncthreads();

    float fj[2][Dd], b3[2], b6[2];
#pragma unroll
    for (int t = 0; t < 2; t++) {
        float s3 = 0.f, s6 = 0.f;
#pragma unroll
        for (int d = 0; d < Dd; d++) {
            float v = feat[d * N + j0 + t];
            fj[t][d] = v;
            if (d < 3) s3 += v * v; else s6 += v * v;
        }
        b3[t] = s3;
        b6[t] = s3 + s6;
    }

#pragma unroll 4
    for (int r = 0; r < BI; r++) {
        float ksp[2], kbl[2];
#pragma unroll
        for (int t = 0; t < 2; t++) {
            float s3 = 0.f, s6 = 0.f;
#pragma unroll
            for (int d = 0; d < 3; d++) s3 = fmaf(fis[d][r], fj[t][d], s3);
            s6 = s3;
#pragma unroll
            for (int d = 3; d < Dd; d++) s6 = fmaf(fis[d][r], fj[t][d], s6);
            float d3 = a3s[r] + b3[t] - 2.f * s3;
            float d6 = a6s[r] + b6[t] - 2.f * s6;
            ksp[t] = __expf(d3 * (-1.f / 128.f));
            kbl[t] = __expf(-0.5f * d6);
        }
        size_t off = (size_t)(ib + r) * N + j0;
        *(__half2*)&g_Ksp[off] = __floats2half2_rn(ksp[0], ksp[1]);
        *(__half2*)&g_Kbl[off] = __floats2half2_rn(kbl[0], kbl[1]);
    }
}

// ---------------------------------------------------------------------------
__global__ void ab_k(const float* __restrict__ sw, const float* __restrict__ bw,
                     const float* __restrict__ cm) {
    int t = threadIdx.x;
    if (t < C * C) {
        int r = t / C, c = t % C;
        float a = 0.f, b = 0.f;
        for (int k = 0; k < C; k++) {
            a += cm[r * C + k] * sw[k * C + c];
            b += cm[r * C + k] * bw[k * C + c];
        }
        g_A[t] = a;
        g_B[t] = b;
    }
}

// ---------------------------------------------------------------------------
// Initial softmax over classes (from unaries); zeroes gemv accumulators.
// ---------------------------------------------------------------------------
__global__ __launch_bounds__(256) void softmax_k(const float* __restrict__ qin) {
    int i = blockIdx.x * blockDim.x + threadIdx.x;
    if (i >= N) return;
    float v[C];
    float m = -1e30f;
#pragma unroll
    for (int c = 0; c < C; c++) {
        v[c] = qin[c * N + i];
        m = fmaxf(m, v[c]);
    }
    float s = 0.f;
#pragma unroll
    for (int c = 0; c < C; c++) {
        v[c] = __expf(v[c] - m);
        s += v[c];
    }
    float inv = 1.0f / s;
#pragma unroll
    for (int c = 0; c < C; c++) {
        g_P[c * N + i] = v[c] * inv;
        g_OSP[c * N + i] = 0.f;
        g_OBL[c * N + i] = 0.f;
    }
}

// ---------------------------------------------------------------------------
// Out[c,i] += sum_{j in chunk} K[j,i] * P[c,j]   (K symmetry: K[j,i]=K[i,j])
// Lane owns i-columns (coalesced LDG over K rows); P[c,j] is warp-uniform
// broadcast LDS. Thread: 2 i-pairs (ia, ia+64). Commit via float2 atomics.
// grid = (N/IT, N/JC, 2); block = 128 (4 warps x 128 i); 6 blocks/SM target.
// ---------------------------------------------------------------------------
__global__ __launch_bounds__(128, 6) void gemv_k() {
    __shared__ unsigned long long psm[C][JC];   // duplicated (p,p) pairs, 20 KB

    const __half* __restrict__ K = blockIdx.z ? g_Kbl : g_Ksp;
    float* __restrict__ outp = blockIdx.z ? g_OBL : g_OSP;

    const int cb = blockIdx.y * JC;
    const int tid = threadIdx.x;

    // stage P chunk, duplicating each value into both f32x2 lanes
    for (int idx = tid; idx < C * JC; idx += 128) {
        int c = idx >> 8, j = idx & (JC - 1);
        float p = g_P[c * N + cb + j];
        psm[c][j] = pk2(p, p);
    }
    __syncthreads();

    const int warp = tid >> 5, lane = tid & 31;
    const int ia = blockIdx.x * IT + warp * 128 + 2 * lane;

    unsigned long long acc0[C], acc1[C];
#pragma unroll
    for (int c = 0; c < C; c++) { acc0[c] = 0ull; acc1[c] = 0ull; }

    const __half* __restrict__ kb = K + (size_t)cb * N + ia;

    for (int jj = 0; jj < JC; jj += 4) {
        unsigned int kra[4], krb[4];
#pragma unroll
        for (int u = 0; u < 4; u++) {
            const __half* rp = kb + (size_t)(jj + u) * N;
            kra[u] = *(const unsigned int*)rp;
            krb[u] = *(const unsigned int*)(rp + 64);
        }
#pragma unroll
        for (int u = 0; u < 4; u++) {
            float2 fa = __half22float2(*(__half2*)&kra[u]);
            float2 fb = __half22float2(*(__half2*)&krb[u]);
            unsigned long long kva = pk2(fa.x, fa.y);
            unsigned long long kvb = pk2(fb.x, fb.y);
#pragma unroll
            for (int c = 0; c < C; c++) {
                unsigned long long pv = psm[c][jj + u];
                acc0[c] = ffma2(kva, pv, acc0[c]);
                acc1[c] = ffma2(kvb, pv, acc1[c]);
            }
        }
    }

    // commit with vector atomics (each thread owns consecutive pairs)
#pragma unroll
    for (int c = 0; c < C; c++) {
        float* o = outp + c * N + ia;
        atomicAdd((float2*)o, upk2(acc0[c]));
        atomicAdd((float2*)(o + 64), upk2(acc1[c]));
    }
}

// ---------------------------------------------------------------------------
// Fused: q = unaries - (A @ sp + B @ bl); write q; if not last iteration,
// softmax(q) -> P and zero the accumulators for the next gemv.
// ---------------------------------------------------------------------------
__global__ __launch_bounds__(256) void update_k(const float* __restrict__ unaries,
                                                float* __restrict__ qout,
                                                int last) {
    __shared__ float As[C * C], Bs[C * C];
    if (threadIdx.x < C * C) {
        As[threadIdx.x] = g_A[threadIdx.x];
        Bs[threadIdx.x] = g_B[threadIdx.x];
    }
    __syncthreads();

    int i = blockIdx.x * blockDim.x + threadIdx.x;
    if (i >= N) return;

    float sp[C], bl[C];
#pragma unroll
    for (int k = 0; k < C; k++) {
        sp[k] = g_OSP[k * N + i];
        bl[k] = g_OBL[k * N + i];
    }

    float q[C];
#pragma unroll
    for (int c = 0; c < C; c++) {
        float pair = 0.f;
#pragma unroll
        for (int k = 0; k < C; k++)
            pair += As[c * C + k] * sp[k] + Bs[c * C + k] * bl[k];
        q[c] = unaries[c * N + i] - pair;
        qout[c * N + i] = q[c];
    }

    if (last) return;

    float m = -1e30f;
#pragma unroll
    for (int c = 0; c < C; c++) m = fmaxf(m, q[c]);
    float s = 0.f;
#pragma unroll
    for (int c = 0; c < C; c++) {
        q[c] = __expf(q[c] - m);
        s += q[c];
    }
    float inv = 1.0f / s;
#pragma unroll
    for (int c = 0; c < C; c++) {
        g_P[c * N + i] = q[c] * inv;
        g_OSP[c * N + i] = 0.f;
        g_OBL[c * N + i] = 0.f;
    }
}

// ---------------------------------------------------------------------------
extern "C" void kernel_launch(void* const* d_in, const int* in_sizes, int n_in,
                              void* d_out, int out_size) {
    const float* unaries = (const float*)d_in[0];
    const float* feat = (const float*)d_in[1];
    const float* sw = (const float*)d_in[2];
    const float* bw = (const float*)d_in[3];
    const float* cm = (const float*)d_in[4];
    float* qout = (float*)d_out;

    build_K<<<dim3(N / 512, N / BI), 256>>>(feat);
    ab_k<<<1, 128>>>(sw, bw, cm);

    softmax_k<<<N / 256, 256>>>(unaries);
    for (int it = 0; it < 5; it++) {
        gemv_k<<<dim3(N / IT, N / JC, 2), 128>>>();
        update_k<<<N / 256, 256>>>(unaries, qout, it == 4);
    }
}

// round 11
// speedup vs baseline: 1.6335x; 1.6335x over previous
#include <cuda_runtime.h>
#include <cuda_fp16.h>

#define N 8192
#define C 10
#define Dd 6
#define JC 512    // j-chunk per gemv block
#define IT 512    // i-tile per gemv block (4 warps x 128)
#define BI 64

__device__ __half g_Ksp[(size_t)N * N];   // 134 MB
__device__ __half g_Kbl[(size_t)N * N];   // 134 MB
__device__ float g_P[C * N];
__device__ float g_OSP[C * N];
__device__ float g_OBL[C * N];
__device__ float g_A[C * C];
__device__ float g_B[C * C];

// ---- f32x2 packed helpers ----
__device__ __forceinline__ unsigned long long pk2(float lo, float hi) {
    unsigned long long r;
    asm("mov.b64 %0, {%1, %2};" : "=l"(r) : "f"(lo), "f"(hi));
    return r;
}
__device__ __forceinline__ float2 upk2(unsigned long long v) {
    float2 r;
    asm("mov.b64 {%0, %1}, %2;" : "=f"(r.x), "=f"(r.y) : "l"(v));
    return r;
}
__device__ __forceinline__ unsigned long long ffma2(unsigned long long a,
                                                    unsigned long long b,
                                                    unsigned long long c) {
    unsigned long long d;
    asm("fma.rn.f32x2 %0, %1, %2, %3;" : "=l"(d) : "l"(a), "l"(b), "l"(c));
    return d;
}

// ---------------------------------------------------------------------------
// Build both kernel matrices (fp16) once. Dot-product distance form.
// ---------------------------------------------------------------------------
__global__ __launch_bounds__(256) void build_K(const float* __restrict__ feat) {
    __shared__ float fis[Dd][BI];
    __shared__ float a3s[BI], a6s[BI];

    const int ib = blockIdx.y * BI;
    const int jp = blockIdx.x * 256 + threadIdx.x;
    const int j0 = jp * 2;

    if (threadIdx.x < BI) {
        float s3 = 0.f, s6 = 0.f;
#pragma unroll
        for (int d = 0; d < Dd; d++) {
            float v = feat[d * N + ib + threadIdx.x];
            fis[d][threadIdx.x] = v;
            if (d < 3) s3 += v * v; else s6 += v * v;
        }
        a3s[threadIdx.x] = s3;
        a6s[threadIdx.x] = s3 + s6;
    }
    __syncthreads();

    float fj[2][Dd], b3[2], b6[2];
#pragma unroll
    for (int t = 0; t < 2; t++) {
        float s3 = 0.f, s6 = 0.f;
#pragma unroll
        for (int d = 0; d < Dd; d++) {
            float v = feat[d * N + j0 + t];
            fj[t][d] = v;
            if (d < 3) s3 += v * v; else s6 += v * v;
        }
        b3[t] = s3;
        b6[t] = s3 + s6;
    }

#pragma unroll 4
    for (int r = 0; r < BI; r++) {
        float ksp[2], kbl[2];
#pragma unroll
        for (int t = 0; t < 2; t++) {
            float s3 = 0.f, s6 = 0.f;
#pragma unroll
            for (int d = 0; d < 3; d++) s3 = fmaf(fis[d][r], fj[t][d], s3);
            s6 = s3;
#pragma unroll
            for (int d = 3; d < Dd; d++) s6 = fmaf(fis[d][r], fj[t][d], s6);
            float d3 = a3s[r] + b3[t] - 2.f * s3;
            float d6 = a6s[r] + b6[t] - 2.f * s6;
            ksp[t] = __expf(d3 * (-1.f / 128.f));
            kbl[t] = __expf(-0.5f * d6);
        }
        size_t off = (size_t)(ib + r) * N + j0;
        *(__half2*)&g_Ksp[off] = __floats2half2_rn(ksp[0], ksp[1]);
        *(__half2*)&g_Kbl[off] = __floats2half2_rn(kbl[0], kbl[1]);
    }
}

// ---------------------------------------------------------------------------
__global__ void ab_k(const float* __restrict__ sw, const float* __restrict__ bw,
                     const float* __restrict__ cm) {
    int t = threadIdx.x;
    if (t < C * C) {
        int r = t / C, c = t % C;
        float a = 0.f, b = 0.f;
        for (int k = 0; k < C; k++) {
            a += cm[r * C + k] * sw[k * C + c];
            b += cm[r * C + k] * bw[k * C + c];
        }
        g_A[t] = a;
        g_B[t] = b;
    }
}

// ---------------------------------------------------------------------------
// Initial softmax over classes (from unaries); zeroes gemv accumulators.
// ---------------------------------------------------------------------------
__global__ __launch_bounds__(256) void softmax_k(const float* __restrict__ qin) {
    int i = blockIdx.x * blockDim.x + threadIdx.x;
    if (i >= N) return;
    float v[C];
    float m = -1e30f;
#pragma unroll
    for (int c = 0; c < C; c++) {
        v[c] = qin[c * N + i];
        m = fmaxf(m, v[c]);
    }
    float s = 0.f;
#pragma unroll
    for (int c = 0; c < C; c++) {
        v[c] = __expf(v[c] - m);
        s += v[c];
    }
    float inv = 1.0f / s;
#pragma unroll
    for (int c = 0; c < C; c++) {
        g_P[c * N + i] = v[c] * inv;
        g_OSP[c * N + i] = 0.f;
        g_OBL[c * N + i] = 0.f;
    }
}

// ---------------------------------------------------------------------------
// Out[c,i] += sum_{j in chunk} K[j,i] * P[c,j]   (K symmetry: K[j,i]=K[i,j])
// Lane owns i-columns (coalesced LDG over K rows); P[c,j] is warp-uniform
// broadcast LDS. Thread: 2 i-pairs (ia, ia+64). 16 LDG front-batched per
// unroll-8 step for MLP. Commit via float2 atomics.
// grid = (N/IT, N/JC, 2); block = 128 (4 warps x 128 i).
// ---------------------------------------------------------------------------
__global__ __launch_bounds__(128) void gemv_k() {
    __shared__ unsigned long long psm[C][JC];   // duplicated (p,p) pairs, 40 KB

    const __half* __restrict__ K = blockIdx.z ? g_Kbl : g_Ksp;
    float* __restrict__ outp = blockIdx.z ? g_OBL : g_OSP;

    const int cb = blockIdx.y * JC;
    const int tid = threadIdx.x;

    // stage P chunk, duplicating each value into both f32x2 lanes
    for (int idx = tid; idx < C * JC; idx += 128) {
        int c = idx >> 9, j = idx & (JC - 1);
        float p = g_P[c * N + cb + j];
        psm[c][j] = pk2(p, p);
    }
    __syncthreads();

    const int warp = tid >> 5, lane = tid & 31;
    const int ia = blockIdx.x * IT + warp * 128 + 2 * lane;

    unsigned long long acc0[C], acc1[C];
#pragma unroll
    for (int c = 0; c < C; c++) { acc0[c] = 0ull; acc1[c] = 0ull; }

    const __half* __restrict__ kb = K + (size_t)cb * N + ia;

    for (int jj = 0; jj < JC; jj += 8) {
        unsigned int kra[8], krb[8];
#pragma unroll
        for (int u = 0; u < 8; u++) {
            const __half* rp = kb + (size_t)(jj + u) * N;
            kra[u] = *(const unsigned int*)rp;
            krb[u] = *(const unsigned int*)(rp + 64);
        }
#pragma unroll
        for (int u = 0; u < 8; u++) {
            float2 fa = __half22float2(*(__half2*)&kra[u]);
            float2 fb = __half22float2(*(__half2*)&krb[u]);
            unsigned long long kva = pk2(fa.x, fa.y);
            unsigned long long kvb = pk2(fb.x, fb.y);
#pragma unroll
            for (int c = 0; c < C; c++) {
                unsigned long long pv = psm[c][jj + u];
                acc0[c] = ffma2(kva, pv, acc0[c]);
                acc1[c] = ffma2(kvb, pv, acc1[c]);
            }
        }
    }

    // commit with vector atomics (each thread owns consecutive pairs)
#pragma unroll
    for (int c = 0; c < C; c++) {
        float* o = outp + c * N + ia;
        atomicAdd((float2*)o, upk2(acc0[c]));
        atomicAdd((float2*)(o + 64), upk2(acc1[c]));
    }
}

// ---------------------------------------------------------------------------
// Fused: q = unaries - (A @ sp + B @ bl); write q; if not last iteration,
// softmax(q) -> P and zero the accumulators for the next gemv.
// ---------------------------------------------------------------------------
__global__ __launch_bounds__(256) void update_k(const float* __restrict__ unaries,
                                                float* __restrict__ qout,
                                                int last) {
    __shared__ float As[C * C], Bs[C * C];
    if (threadIdx.x < C * C) {
        As[threadIdx.x] = g_A[threadIdx.x];
        Bs[threadIdx.x] = g_B[threadIdx.x];
    }
    __syncthreads();

    int i = blockIdx.x * blockDim.x + threadIdx.x;
    if (i >= N) return;

    float sp[C], bl[C];
#pragma unroll
    for (int k = 0; k < C; k++) {
        sp[k] = g_OSP[k * N + i];
        bl[k] = g_OBL[k * N + i];
    }

    float q[C];
#pragma unroll
    for (int c = 0; c < C; c++) {
        float pair = 0.f;
#pragma unroll
        for (int k = 0; k < C; k++)
            pair += As[c * C + k] * sp[k] + Bs[c * C + k] * bl[k];
        q[c] = unaries[c * N + i] - pair;
        qout[c * N + i] = q[c];
    }

    if (last) return;

    float m = -1e30f;
#pragma unroll
    for (int c = 0; c < C; c++) m = fmaxf(m, q[c]);
    float s = 0.f;
#pragma unroll
    for (int c = 0; c < C; c++) {
        q[c] = __expf(q[c] - m);
        s += q[c];
    }
    float inv = 1.0f / s;
#pragma unroll
    for (int c = 0; c < C; c++) {
        g_P[c * N + i] = q[c] * inv;
        g_OSP[c * N + i] = 0.f;
        g_OBL[c * N + i] = 0.f;
    }
}

// ---------------------------------------------------------------------------
extern "C" void kernel_launch(void* const* d_in, const int* in_sizes, int n_in,
                              void* d_out, int out_size) {
    const float* unaries = (const float*)d_in[0];
    const float* feat = (const float*)d_in[1];
    const float* sw = (const float*)d_in[2];
    const float* bw = (const float*)d_in[3];
    const float* cm = (const float*)d_in[4];
    float* qout = (float*)d_out;

    build_K<<<dim3(N / 512, N / BI), 256>>>(feat);
    ab_k<<<1, 128>>>(sw, bw, cm);

    softmax_k<<<N / 256, 256>>>(unaries);
    for (int it = 0; it < 5; it++) {
        gemv_k<<<dim3(N / IT, N / JC, 2), 128>>>();
        update_k<<<N / 256, 256>>>(unaries, qout, it == 4);
    }
}